// round 1
// baseline (speedup 1.0000x reference)
#include <cuda_runtime.h>
#include <cstdint>
#include <cstddef>

#define DEV_INLINE __device__ __forceinline__

constexpr int kB = 4, kC = 128, kH = 128, kW = 128;
constexpr int kHW = kH * kW;

// ---- scratch layout (floats) ----
constexpr size_t O_XT    = 0;          // x in NHWC          [4,128,128,128]
constexpr size_t O_H1    = 8388608;    // stage1 out NHWC
constexpr size_t O_H2    = 16777216;   // resblock out NHWC
constexpr size_t O_H3    = 25165824;   // deform out NHWC
constexpr size_t O_OFF   = 33554432;   // offset conv out NHWC [4,128,128,64]
constexpr size_t O_WT1   = 37748736;   // 9*128*128
constexpr size_t O_WT2   = 37896192;
constexpr size_t O_WTDC  = 38043648;
constexpr size_t O_WTOFF = 38191104;   // 9*128*64
constexpr size_t O_WTCV  = 38264832;   // 128*128
constexpr size_t O_SC    = 38281216;   // s1,t1,s2,t2,s3,t3,s4,t4 (8*128) + soff,toff (2*64)
constexpr size_t SCRATCH = 38282368;

__device__ float g_buf[SCRATCH];

// ---- f32x2 helpers (Blackwell packed fp32) ----
DEV_INLINE unsigned long long dup2(float x) {
    unsigned long long r;
    asm("mov.b64 %0, {%1,%1};" : "=l"(r) : "f"(x));
    return r;
}
DEV_INLINE float2 unpack2(unsigned long long v) {
    float2 r;
    asm("mov.b64 {%0,%1}, %2;" : "=f"(r.x), "=f"(r.y) : "l"(v));
    return r;
}
DEV_INLINE void fma2(unsigned long long& d, unsigned long long a, unsigned long long b) {
    asm("fma.rn.f32x2 %0, %1, %2, %0;" : "+l"(d) : "l"(a), "l"(b));
}

// ======================= prep kernels =======================

__global__ void prep_bn_k(const float* __restrict__ bnp, const float* __restrict__ bias,
                          float* __restrict__ sc, float* __restrict__ sh) {
    int c = threadIdx.x;
    float g = bnp[c], be = bnp[kC + c], m = bnp[2 * kC + c], va = bnp[3 * kC + c];
    float s = g / sqrtf(va + 1e-5f);
    float t = be - m * s;
    if (bias) t += bias[c] * s;   // bn(conv + bias) = conv*s + (t + bias*s)
    sc[c] = s; sh[c] = t;
}

__global__ void prep_off_k(const float* __restrict__ offb,
                           float* __restrict__ sc, float* __restrict__ sh) {
    int c = threadIdx.x;   // 64 threads
    sc[c] = 1.f;
    sh[c] = (c < 54) ? offb[c] : 0.f;
}

// w [OC][128][3][3]  ->  wt [9][128][OCP]  (tap-major, ci, oc) ; pad oc with zeros
__global__ void wtrans3_k(const float* __restrict__ w, float* __restrict__ wt,
                          int OC, int OCP) {
    int idx = blockIdx.x * 256 + threadIdx.x;
    if (idx >= 9 * kC * OCP) return;
    int oc  = idx % OCP;
    int ci  = (idx / OCP) % kC;
    int tap = idx / (OCP * kC);
    wt[idx] = (oc < OC) ? w[(oc * kC + ci) * 9 + tap] : 0.f;
}

// w [OC][128]  ->  wt [128][OC]
__global__ void wtrans1_k(const float* __restrict__ w, float* __restrict__ wt) {
    int idx = blockIdx.x * 256 + threadIdx.x;   // 16384
    int oc = idx & (kC - 1), ci = idx >> 7;
    wt[idx] = w[oc * kC + ci];
}

// NCHW -> NHWC
__global__ void to_nhwc_k(const float* __restrict__ in, float* __restrict__ out) {
    __shared__ float t[32][33];
    int b = blockIdx.z, c0 = blockIdx.y * 32, p0 = blockIdx.x * 32;
    int tx = threadIdx.x, ty = threadIdx.y;
#pragma unroll
    for (int k = 0; k < 32; k += 8)
        t[ty + k][tx] = in[(size_t)(b * kC + c0 + ty + k) * kHW + p0 + tx];
    __syncthreads();
#pragma unroll
    for (int k = 0; k < 32; k += 8)
        out[(size_t)(b * kHW + p0 + ty + k) * kC + c0 + tx] = t[tx][ty + k];
}

// ======================= conv (implicit GEMM, NHWC) =======================
// Tile: 64 pixels (one row segment) x NT output channels. 256 threads.
// EPI: 0 = relu(v*s+t)         (stage1)
//      1 = relu(v*s+t + res)   (stage2, res NHWC stride NT)
//      2 = v*s+t               (offset conv, raw)
//      4 = leaky(v*s+t)+x, NCHW residual/store (final 1x1)
template <int NT, int EPI, int KS>
__global__ void __launch_bounds__(256)
conv_k(const float* __restrict__ in, const float* __restrict__ wt,
       const float* __restrict__ scale, const float* __restrict__ shift,
       const float* __restrict__ res, float* __restrict__ out) {
    constexpr int PIX_T = (NT == 128) ? 8 : 4;
    constexpr int NPAIR = PIX_T / 2;
    constexpr int OCG   = NT / 4;
    constexpr int CK    = 16;

    __shared__ __align__(16) float A[CK][72];
    __shared__ __align__(16) float Bw[CK][NT];

    const int w0  = blockIdx.x * 64;
    const int h   = blockIdx.y;
    const int b   = blockIdx.z;
    const int tid = threadIdx.x;
    const int ocq = tid % OCG;
    const int pixq = tid / OCG;
    const int oc   = ocq * 4;
    const int pix0 = pixq * PIX_T;
    const int lp = tid >> 2;          // pixel 0..63 for A loads
    const int lc = (tid & 3) * 4;     // ci offset for A loads

    unsigned long long acc[NPAIR][4];
#pragma unroll
    for (int i = 0; i < NPAIR; i++)
#pragma unroll
        for (int j = 0; j < 4; j++) acc[i][j] = 0ULL;

#pragma unroll 1
    for (int tap = 0; tap < KS * KS; tap++) {
        const int ty = (KS == 3) ? tap / 3 : 1;
        const int tx = (KS == 3) ? tap % 3 : 1;
        const int row  = h + ty - 1;
        const int colb = w0 + tx - 1;
        const bool rowok = (KS == 1) || (row >= 0 && row < kH);
        const float* inrow = in + (long long)(b * kHW + row * kW) * kC;
#pragma unroll 1
        for (int cb = 0; cb < kC; cb += CK) {
            // A tile: [ci][pix]
            {
                float4 v = make_float4(0.f, 0.f, 0.f, 0.f);
                int col = colb + lp;
                if (rowok && col >= 0 && col < kW)
                    v = *(const float4*)(inrow + (size_t)col * kC + cb + lc);
                A[lc + 0][lp] = v.x; A[lc + 1][lp] = v.y;
                A[lc + 2][lp] = v.z; A[lc + 3][lp] = v.w;
            }
            // B tile: [ci][oc] — contiguous in wt
            {
                const float4* src = (const float4*)(wt + (size_t)(tap * kC + cb) * NT);
                float4* dst = (float4*)(&Bw[0][0]);
#pragma unroll
                for (int i = tid; i < CK * NT / 4; i += 256) dst[i] = src[i];
            }
            __syncthreads();
#pragma unroll
            for (int ci = 0; ci < CK; ci++) {
                float4 wv = *(const float4*)(&Bw[ci][oc]);
                unsigned long long wd0 = dup2(wv.x), wd1 = dup2(wv.y);
                unsigned long long wd2 = dup2(wv.z), wd3 = dup2(wv.w);
#pragma unroll
                for (int pp = 0; pp < NPAIR; pp++) {
                    unsigned long long a =
                        *(const unsigned long long*)(&A[ci][pix0 + 2 * pp]);
                    fma2(acc[pp][0], a, wd0);
                    fma2(acc[pp][1], a, wd1);
                    fma2(acc[pp][2], a, wd2);
                    fma2(acc[pp][3], a, wd3);
                }
            }
            __syncthreads();
        }
    }

    // unpack accumulators
    float vv[PIX_T][4];
#pragma unroll
    for (int pp = 0; pp < NPAIR; pp++)
#pragma unroll
        for (int j = 0; j < 4; j++) {
            float2 u = unpack2(acc[pp][j]);
            vv[2 * pp][j] = u.x; vv[2 * pp + 1][j] = u.y;
        }

    float4 sc4 = *(const float4*)(scale + oc);
    float4 sh4 = *(const float4*)(shift + oc);
    float scv[4] = {sc4.x, sc4.y, sc4.z, sc4.w};
    float shv[4] = {sh4.x, sh4.y, sh4.z, sh4.w};

    if (EPI == 4) {
        // final: leaky + NCHW residual, NCHW store
#pragma unroll
        for (int j = 0; j < 4; j++) {
            const float* xr = res + (size_t)(b * kC + oc + j) * kHW + h * kW + w0 + pix0;
            float* orow     = out + (size_t)(b * kC + oc + j) * kHW + h * kW + w0 + pix0;
#pragma unroll
            for (int p = 0; p < PIX_T; p++) {
                float t = vv[p][j] * scv[j] + shv[j];
                t = (t > 0.f) ? t : 0.1f * t;
                orow[p] = xr[p] + t;
            }
        }
    } else {
#pragma unroll
        for (int p = 0; p < PIX_T; p++) {
            int wcol = w0 + pix0 + p;
            float rr[4] = {0.f, 0.f, 0.f, 0.f};
            if (EPI == 1) {
                float4 r4 = *(const float4*)(res + (size_t)(b * kHW + h * kW + wcol) * NT + oc);
                rr[0] = r4.x; rr[1] = r4.y; rr[2] = r4.z; rr[3] = r4.w;
            }
            float o[4];
#pragma unroll
            for (int j = 0; j < 4; j++) {
                float t = vv[p][j] * scv[j] + shv[j];
                if (EPI == 1) t += rr[j];
                if (EPI == 0 || EPI == 1) t = fmaxf(t, 0.f);
                o[j] = t;
            }
            *(float4*)(out + (size_t)(b * kHW + h * kW + wcol) * NT + oc) =
                make_float4(o[0], o[1], o[2], o[3]);
        }
    }
}

// ======================= modulated deformable conv =======================
// Tile: 32 pixels (row segment) x 128 oc. Per (d,k): sample 32x64 tile to smem,
// GEMM against 64x128 weight tile. Epilogue: leaky(bn1(v + dc_b)) -> NHWC.
__global__ void __launch_bounds__(256)
deform_k(const float* __restrict__ h2, const float* __restrict__ off,
         const float* __restrict__ wt, const float* __restrict__ scale,
         const float* __restrict__ shift, float* __restrict__ out) {
    __shared__ __align__(16) float S[64][40];     // [cg][pix]
    __shared__ __align__(16) float Wm[64][128];   // [cg][oc]

    const int w0  = blockIdx.x * 32;
    const int h   = blockIdx.y;
    const int b   = blockIdx.z;
    const int tid = threadIdx.x;
    const int ocq = tid & 31, pixq = tid >> 5;
    const int oc = ocq * 4, pix0 = pixq * 4;
    const int sp  = tid & 31;            // sampling pixel = lane (conflict-free STS)
    const int sc8 = (tid >> 5) * 8;      // 8-channel slab per warp

    unsigned long long acc[2][4];
#pragma unroll
    for (int i = 0; i < 2; i++)
#pragma unroll
        for (int j = 0; j < 4; j++) acc[i][j] = 0ULL;

    const float* offp = off + (size_t)(b * kHW + h * kW + w0 + sp) * 64;
    const int wx = w0 + sp;

#pragma unroll 1
    for (int d = 0; d < 2; d++) {
#pragma unroll 1
        for (int k = 0; k < 9; k++) {
            // ---- bilinear sampling for pixel sp, channels sc8..sc8+7, group d ----
            float oy = offp[d * 18 + 2 * k];
            float ox = offp[d * 18 + 2 * k + 1];
            float ml = offp[36 + d * 9 + k];
            float m  = 1.f / (1.f + __expf(-ml));
            float py = oy + (float)(h + k / 3 - 1);
            float px = ox + (float)(wx + k % 3 - 1);
            float y0f = floorf(py), x0f = floorf(px);
            float fy = py - y0f, fx = px - x0f;
            int y0 = (int)y0f, x0 = (int)x0f;
            float w00 = (1.f - fy) * (1.f - fx) * m;
            float w01 = (1.f - fy) * fx * m;
            float w10 = fy * (1.f - fx) * m;
            float w11 = fy * fx * m;
            const float* basep = h2 + (size_t)b * kHW * kC + d * 64 + sc8;
            float r[8] = {0.f, 0.f, 0.f, 0.f, 0.f, 0.f, 0.f, 0.f};
            auto samp = [&](int y, int x, float wgt) {
                if (y >= 0 && y < kH && x >= 0 && x < kW) {
                    const float4* p4 = (const float4*)(basep + (size_t)(y * kW + x) * kC);
                    float4 u0 = p4[0], u1 = p4[1];
                    r[0] += wgt * u0.x; r[1] += wgt * u0.y;
                    r[2] += wgt * u0.z; r[3] += wgt * u0.w;
                    r[4] += wgt * u1.x; r[5] += wgt * u1.y;
                    r[6] += wgt * u1.z; r[7] += wgt * u1.w;
                }
            };
            samp(y0,     x0,     w00);
            samp(y0,     x0 + 1, w01);
            samp(y0 + 1, x0,     w10);
            samp(y0 + 1, x0 + 1, w11);
#pragma unroll
            for (int j = 0; j < 8; j++) S[sc8 + j][sp] = r[j];

            // ---- stage weights [cg 0..63][oc 0..127] for (d,k) ----
            {
                const float4* src = (const float4*)(wt + (size_t)(k * kC + d * 64) * kC);
                float4* dst = (float4*)(&Wm[0][0]);
#pragma unroll
                for (int i = tid; i < 64 * kC / 4; i += 256) dst[i] = src[i];
            }
            __syncthreads();

            // ---- GEMM 32pix x 128oc x 64cg ----
#pragma unroll
            for (int cg = 0; cg < 64; cg++) {
                unsigned long long a0 = *(const unsigned long long*)(&S[cg][pix0]);
                unsigned long long a1 = *(const unsigned long long*)(&S[cg][pix0 + 2]);
                float4 wv = *(const float4*)(&Wm[cg][oc]);
                unsigned long long wd0 = dup2(wv.x), wd1 = dup2(wv.y);
                unsigned long long wd2 = dup2(wv.z), wd3 = dup2(wv.w);
                fma2(acc[0][0], a0, wd0); fma2(acc[0][1], a0, wd1);
                fma2(acc[0][2], a0, wd2); fma2(acc[0][3], a0, wd3);
                fma2(acc[1][0], a1, wd0); fma2(acc[1][1], a1, wd1);
                fma2(acc[1][2], a1, wd2); fma2(acc[1][3], a1, wd3);
            }
            __syncthreads();
        }
    }

    // epilogue: leaky(v*s + t) -> NHWC
    float4 sc4 = *(const float4*)(scale + oc);
    float4 sh4 = *(const float4*)(shift + oc);
    float scv[4] = {sc4.x, sc4.y, sc4.z, sc4.w};
    float shv[4] = {sh4.x, sh4.y, sh4.z, sh4.w};
#pragma unroll
    for (int pp = 0; pp < 2; pp++) {
        float2 u[4];
#pragma unroll
        for (int j = 0; j < 4; j++) u[j] = unpack2(acc[pp][j]);
#pragma unroll
        for (int half = 0; half < 2; half++) {
            int wcol = w0 + pix0 + 2 * pp + half;
            float o[4];
#pragma unroll
            for (int j = 0; j < 4; j++) {
                float t = (half ? u[j].y : u[j].x) * scv[j] + shv[j];
                o[j] = (t > 0.f) ? t : 0.1f * t;
            }
            *(float4*)(out + (size_t)(b * kHW + h * kW + wcol) * kC + oc) =
                make_float4(o[0], o[1], o[2], o[3]);
        }
    }
}

// ======================= launch =======================

extern "C" void kernel_launch(void* const* d_in, const int* in_sizes, int n_in,
                              void* d_out, int out_size) {
    (void)in_sizes; (void)n_in; (void)out_size;
    const float* x      = (const float*)d_in[0];
    const float* rb_w1  = (const float*)d_in[1];
    const float* rb_b1  = (const float*)d_in[2];
    const float* rb_bn1 = (const float*)d_in[3];
    const float* rb_w2  = (const float*)d_in[4];
    const float* rb_b2  = (const float*)d_in[5];
    const float* rb_bn2 = (const float*)d_in[6];
    const float* off_w  = (const float*)d_in[7];
    const float* off_b  = (const float*)d_in[8];
    const float* dc_w   = (const float*)d_in[9];
    const float* dc_b   = (const float*)d_in[10];
    const float* bn1    = (const float*)d_in[11];
    const float* cv2_w  = (const float*)d_in[12];
    const float* bn2    = (const float*)d_in[13];
    float* out = (float*)d_out;

    float* base = nullptr;
    cudaGetSymbolAddress((void**)&base, g_buf);
    float* xt    = base + O_XT;
    float* h1    = base + O_H1;
    float* h2    = base + O_H2;
    float* h3    = base + O_H3;
    float* offb_ = base + O_OFF;
    float* wt1   = base + O_WT1;
    float* wt2   = base + O_WT2;
    float* wtdc  = base + O_WTDC;
    float* wtoff = base + O_WTOFF;
    float* wtcv  = base + O_WTCV;
    float* s1 = base + O_SC;           float* t1 = s1 + kC;
    float* s2 = t1 + kC;               float* t2 = s2 + kC;
    float* s3 = t2 + kC;               float* t3 = s3 + kC;
    float* s4 = t3 + kC;               float* t4 = s4 + kC;
    float* soff = t4 + kC;             float* toff = soff + 64;

    // prep (tiny, deterministic)
    wtrans3_k<<<(9 * kC * kC + 255) / 256, 256>>>(rb_w1, wt1, kC, kC);
    wtrans3_k<<<(9 * kC * kC + 255) / 256, 256>>>(rb_w2, wt2, kC, kC);
    wtrans3_k<<<(9 * kC * kC + 255) / 256, 256>>>(dc_w,  wtdc, kC, kC);
    wtrans3_k<<<(9 * kC * 64 + 255) / 256, 256>>>(off_w, wtoff, 54, 64);
    wtrans1_k<<<(kC * kC) / 256, 256>>>(cv2_w, wtcv);
    prep_bn_k<<<1, kC>>>(rb_bn1, rb_b1, s1, t1);
    prep_bn_k<<<1, kC>>>(rb_bn2, rb_b2, s2, t2);
    prep_bn_k<<<1, kC>>>(bn1, dc_b, s3, t3);
    prep_bn_k<<<1, kC>>>(bn2, nullptr, s4, t4);
    prep_off_k<<<1, 64>>>(off_b, soff, toff);

    // pipeline
    to_nhwc_k<<<dim3(kHW / 32, kC / 32, kB), dim3(32, 8)>>>(x, xt);
    conv_k<128, 0, 3><<<dim3(2, kH, kB), 256>>>(xt, wt1, s1, t1, nullptr, h1);
    conv_k<128, 1, 3><<<dim3(2, kH, kB), 256>>>(h1, wt2, s2, t2, xt, h2);
    conv_k<64, 2, 3><<<dim3(2, kH, kB), 256>>>(h2, wtoff, soff, toff, nullptr, offb_);
    deform_k<<<dim3(4, kH, kB), 256>>>(h2, offb_, wtdc, s3, t3, h3);
    conv_k<128, 4, 1><<<dim3(2, kH, kB), 256>>>(h3, wtcv, s4, t4, x, out);
}

// round 3
// speedup vs baseline: 1.9413x; 1.9413x over previous
#include <cuda_runtime.h>
#include <cuda_bf16.h>
#include <cstdint>
#include <cstddef>

#define DEV_INLINE __device__ __forceinline__
typedef __nv_bfloat16 bf16;

constexpr int kB = 4, kC = 128, kH = 128, kW = 128;
constexpr int kHW = kH * kW;

// ======================= scratch (floats) =======================
constexpr size_t O_XT   = 0;          // x NHWC fp32
constexpr size_t O_H2F  = 8388608;    // h2 NHWC fp32 (deform sampling)
constexpr size_t O_OFFB = 16777216;   // offset conv out NHWC [4,128,128,64] fp32
constexpr size_t O_XHI  = 20971520;   // bf16 arrays (each 8.4M bf16 = 4194304 floats)
constexpr size_t O_XLO  = 25165824;
constexpr size_t O_H1HI = 29360128;
constexpr size_t O_H1LO = 33554432;
constexpr size_t O_H2HI = 37748736;
constexpr size_t O_H2LO = 41943040;
constexpr size_t O_H3HI = 46137344;
constexpr size_t O_H3LO = 50331648;
constexpr size_t O_W1HI = 54525952;
constexpr size_t O_W1LO = 54599680;
constexpr size_t O_W2HI = 54673408;
constexpr size_t O_W2LO = 54747136;
constexpr size_t O_WDHI = 54820864;
constexpr size_t O_WDLO = 54894592;
constexpr size_t O_WOHI = 54968320;
constexpr size_t O_WOLO = 55005184;
constexpr size_t O_WCHI = 55042048;
constexpr size_t O_WCLO = 55050240;
constexpr size_t O_SC   = 55058432;
constexpr size_t SCRATCH= 55060608;

__device__ float g_buf[SCRATCH];

// ======================= PTX helpers =======================
DEV_INLINE uint32_t smem_to_u32(const void* p) {
    uint32_t a;
    asm("{ .reg .u64 t; cvta.to.shared.u64 t, %1; cvt.u32.u64 %0, t; }" : "=r"(a) : "l"(p));
    return a;
}
DEV_INLINE void cp16(uint32_t d, const void* s, bool ok) {
    asm volatile("cp.async.ca.shared.global [%0], [%1], 16, %2;"
                 :: "r"(d), "l"(s), "r"(ok ? 16 : 0));
}
DEV_INLINE void cp_commit() { asm volatile("cp.async.commit_group;" ::: "memory"); }
DEV_INLINE void cp_wait0()  { asm volatile("cp.async.wait_group 0;" ::: "memory"); }
DEV_INLINE void cp_wait1()  { asm volatile("cp.async.wait_group 1;" ::: "memory"); }

DEV_INLINE void ldsm4(uint32_t a, uint32_t& r0, uint32_t& r1, uint32_t& r2, uint32_t& r3) {
    asm volatile("ldmatrix.sync.aligned.m8n8.x4.shared.b16 {%0,%1,%2,%3}, [%4];"
                 : "=r"(r0), "=r"(r1), "=r"(r2), "=r"(r3) : "r"(a));
}
DEV_INLINE void mma16816(float* c, const uint32_t* a, const uint32_t* b) {
    asm volatile("mma.sync.aligned.m16n8k16.row.col.f32.bf16.bf16.f32 "
                 "{%0,%1,%2,%3},{%4,%5,%6,%7},{%8,%9},{%0,%1,%2,%3};"
                 : "+f"(c[0]), "+f"(c[1]), "+f"(c[2]), "+f"(c[3])
                 : "r"(a[0]), "r"(a[1]), "r"(a[2]), "r"(a[3]), "r"(b[0]), "r"(b[1]));
}
DEV_INLINE void split_bf16(float v, bf16& h, bf16& l) {
    h = __float2bfloat16(v);
    l = __float2bfloat16(v - __bfloat162float(h));
}

// mma over one staged K-chunk: MT m-tiles x 8 n-tiles, KS k16 steps, 3 precision passes.
template <int MT, int KS>
DEV_INLINE void mma_chunk(uint32_t Ah, uint32_t Al, uint32_t Bh, uint32_t Bl,
                          int as, int bs, int pxb, int ocb, int lane, float (*acc)[4]) {
    const int r = lane & 7, sel = lane >> 3;
    const int aro = (pxb + (sel & 1) * 8 + r) * as;
    const int bro = (ocb + (sel >> 1) * 8 + r) * bs;
#pragma unroll
    for (int ks = 0; ks < KS; ks++) {
        const int ac = (ks * 16 + (sel >> 1) * 8) * 2;
        const int bc = (ks * 16 + (sel & 1) * 8) * 2;
        uint32_t ah[MT][4], al[MT][4];
#pragma unroll
        for (int mt = 0; mt < MT; mt++) {
            ldsm4(Ah + aro + mt * 16 * as + ac, ah[mt][0], ah[mt][1], ah[mt][2], ah[mt][3]);
            ldsm4(Al + aro + mt * 16 * as + ac, al[mt][0], al[mt][1], al[mt][2], al[mt][3]);
        }
        uint32_t bh[8][2], bl[8][2];
#pragma unroll
        for (int jp = 0; jp < 4; jp++) {
            ldsm4(Bh + bro + jp * 16 * bs + bc,
                  bh[2 * jp][0], bh[2 * jp][1], bh[2 * jp + 1][0], bh[2 * jp + 1][1]);
            ldsm4(Bl + bro + jp * 16 * bs + bc,
                  bl[2 * jp][0], bl[2 * jp][1], bl[2 * jp + 1][0], bl[2 * jp + 1][1]);
        }
#pragma unroll
        for (int mt = 0; mt < MT; mt++)
#pragma unroll
            for (int nt = 0; nt < 8; nt++) {
                float* c = acc[mt * 8 + nt];
                mma16816(c, ah[mt], bh[nt]);
                mma16816(c, ah[mt], bl[nt]);
                mma16816(c, al[mt], bh[nt]);
            }
    }
}

// ======================= prep kernels =======================
__global__ void prep_bn_k(const float* __restrict__ bnp, const float* __restrict__ bias,
                          float* __restrict__ sc, float* __restrict__ sh) {
    int c = threadIdx.x;
    float g = bnp[c], be = bnp[kC + c], m = bnp[2 * kC + c], va = bnp[3 * kC + c];
    float s = g / sqrtf(va + 1e-5f);
    float t = be - m * s;
    if (bias) t += bias[c] * s;
    sc[c] = s; sh[c] = t;
}

__global__ void prep_off_k(const float* __restrict__ offb,
                           float* __restrict__ sc, float* __restrict__ sh) {
    int c = threadIdx.x;
    sc[c] = 1.f;
    sh[c] = (c < 54) ? offb[c] : 0.f;
}

// w [OC][128][3][3] -> [tap][OCP][128] bf16 hi/lo
__global__ void wprep3_k(const float* __restrict__ w, bf16* __restrict__ hi,
                         bf16* __restrict__ lo, int OC, int OCP) {
    int idx = blockIdx.x * 256 + threadIdx.x;
    if (idx >= 9 * OCP * kC) return;
    int ci = idx & 127, oc = (idx >> 7) % OCP, tap = idx / (OCP * kC);
    float v = (oc < OC) ? w[(oc * kC + ci) * 9 + tap] : 0.f;
    bf16 h, l; split_bf16(v, h, l);
    hi[idx] = h; lo[idx] = l;
}

// dc_w [oc][128][9] -> [(d*9+k)][oc][cg64] bf16 hi/lo
__global__ void wprepdc_k(const float* __restrict__ w, bf16* __restrict__ hi,
                          bf16* __restrict__ lo) {
    int idx = blockIdx.x * 256 + threadIdx.x;
    if (idx >= 18 * 128 * 64) return;
    int cg = idx & 63, oc = (idx >> 6) & 127, dk = idx >> 13;
    int d = dk / 9, k = dk % 9;
    float v = w[(oc * kC + d * 64 + cg) * 9 + k];
    bf16 h, l; split_bf16(v, h, l);
    hi[idx] = h; lo[idx] = l;
}

// cv2_w [oc][128] -> [oc][128] bf16 hi/lo
__global__ void wprep1_k(const float* __restrict__ w, bf16* __restrict__ hi,
                         bf16* __restrict__ lo) {
    int idx = blockIdx.x * 256 + threadIdx.x;
    float v = w[idx];
    bf16 h, l; split_bf16(v, h, l);
    hi[idx] = h; lo[idx] = l;
}

// NCHW -> NHWC fp32 + bf16 hi/lo
__global__ void to_nhwc3_k(const float* __restrict__ in, float* __restrict__ outf,
                           bf16* __restrict__ ohi, bf16* __restrict__ olo) {
    __shared__ float t[32][33];
    int b = blockIdx.z, c0 = blockIdx.y * 32, p0 = blockIdx.x * 32;
    int tx = threadIdx.x, ty = threadIdx.y;
#pragma unroll
    for (int k = 0; k < 32; k += 8)
        t[ty + k][tx] = in[(size_t)(b * kC + c0 + ty + k) * kHW + p0 + tx];
    __syncthreads();
#pragma unroll
    for (int k = 0; k < 32; k += 8) {
        float v = t[tx][ty + k];
        size_t o = (size_t)(b * kHW + p0 + ty + k) * kC + c0 + tx;
        outf[o] = v;
        bf16 h, l; split_bf16(v, h, l);
        ohi[o] = h; olo[o] = l;
    }
}

// ======================= conv kernel (implicit GEMM, HMMA) =======================
// CTA: one image row (128 px) x NT oc. K chunks of 32 (tap x ci quarter).
// EPI: 0 relu -> hi/lo   1 relu(+res NHWC) -> f32+hi/lo   2 raw -> f32 (stride 64)
//      4 leaky + x(NCHW) -> NCHW f32
template <int NT, int EPI, int TAPS>
__global__ void __launch_bounds__(256)
mma_conv_k(const bf16* __restrict__ Ahi, const bf16* __restrict__ Alo,
           const bf16* __restrict__ Whi, const bf16* __restrict__ Wlo,
           const float* __restrict__ scale, const float* __restrict__ shift,
           const float* __restrict__ resf, float* __restrict__ outf,
           bf16* __restrict__ outhi, bf16* __restrict__ outlo) {
    constexpr int MT = NT / 64;          // m16 tiles per warp
    constexpr int ASZ = 128 * 80;        // bytes per prec per buf
    constexpr int BSZ = NT * 80;
    constexpr int NC = TAPS * 4;

    extern __shared__ char sm[];
    const uint32_t smA = smem_to_u32(sm);
    const uint32_t smB = smA + 4 * ASZ;

    const int h = blockIdx.x, b = blockIdx.y;
    const int tid = threadIdx.x, wid = tid >> 5, lane = tid & 31;
    const int wm = (NT == 128) ? (wid & 3) : wid;
    const int wn = (NT == 128) ? (wid >> 2) : 0;
    const int pxb = wm * MT * 16;
    const int ocb = wn * 64;

    float acc[MT * 8][4];
#pragma unroll
    for (int i = 0; i < MT * 8; i++)
#pragma unroll
        for (int j = 0; j < 4; j++) acc[i][j] = 0.f;

    auto stage = [&](int c, int s) {
        const int tap = c >> 2, c0 = (c & 3) * 32;
        const int ty = (TAPS == 9) ? tap / 3 - 1 : 0;
        const int tx = (TAPS == 9) ? tap % 3 - 1 : 0;
        const int row = h + ty;
        const bool rok = (row >= 0) && (row < kH);
        // A: 128 px x 32 ci x 2 prec
#pragma unroll
        for (int it = 0; it < 4; it++) {
            int i = it * 256 + tid;
            int prec = i >> 9, rem = i & 511, px = rem >> 2, j = rem & 3;
            int col = px + tx;
            bool ok = rok && col >= 0 && col < kW;
            const bf16* src = (prec ? Alo : Ahi) +
                ((size_t)(b * kHW + (ok ? row * kW + col : 0)) * kC + c0 + j * 8);
            cp16(smA + (s * 2 + prec) * ASZ + px * 80 + j * 16, src, ok);
        }
        // B: NT oc x 32 ci x 2 prec
#pragma unroll
        for (int it = 0; it < NT / 32; it++) {
            int i = it * 256 + tid;
            int prec = i / (NT * 4), rem = i % (NT * 4), oc = rem >> 2, j = rem & 3;
            const bf16* src = (prec ? Wlo : Whi) +
                ((size_t)(tap * NT + oc)) * kC + c0 + j * 8;
            cp16(smB + (s * 2 + prec) * BSZ + oc * 80 + j * 16, src, true);
        }
    };

    stage(0, 0); cp_commit();
#pragma unroll 1
    for (int c = 0; c < NC; c++) {
        const int s = c & 1;
        if (c + 1 < NC) { stage(c + 1, s ^ 1); cp_commit(); cp_wait1(); }
        else cp_wait0();
        __syncthreads();
        mma_chunk<MT, 2>(smA + (s * 2 + 0) * ASZ, smA + (s * 2 + 1) * ASZ,
                         smB + (s * 2 + 0) * BSZ, smB + (s * 2 + 1) * BSZ,
                         80, 80, pxb, ocb, lane, acc);
        __syncthreads();
    }

    // ---- epilogue ----
    const int r4 = lane >> 2, cp2 = (lane & 3) * 2;
    const size_t rowbase = (size_t)(b * kHW + h * kW);
#pragma unroll
    for (int mt = 0; mt < MT; mt++)
#pragma unroll
        for (int nt = 0; nt < 8; nt++) {
            const int oc = ocb + nt * 8 + cp2;
            const float s0 = scale[oc], s1 = scale[oc + 1];
            const float sh0 = shift[oc], sh1 = shift[oc + 1];
#pragma unroll
            for (int hh = 0; hh < 2; hh++) {
                const int px = pxb + mt * 16 + r4 + hh * 8;
                float v0 = acc[mt * 8 + nt][hh * 2 + 0] * s0 + sh0;
                float v1 = acc[mt * 8 + nt][hh * 2 + 1] * s1 + sh1;
                const size_t pix = rowbase + px;
                if (EPI == 1) {
                    float2 rr = *(const float2*)(resf + pix * kC + oc);
                    v0 += rr.x; v1 += rr.y;
                }
                if (EPI == 0 || EPI == 1) { v0 = fmaxf(v0, 0.f); v1 = fmaxf(v1, 0.f); }
                if (EPI == 4) {
                    v0 = (v0 > 0.f) ? v0 : 0.1f * v0;
                    v1 = (v1 > 0.f) ? v1 : 0.1f * v1;
                    size_t i0 = (size_t)(b * kC + oc) * kHW + h * kW + px;
                    outf[i0] = resf[i0] + v0;
                    outf[i0 + kHW] = resf[i0 + kHW] + v1;
                } else if (EPI == 2) {
                    *(float2*)(outf + pix * 64 + oc) = make_float2(v0, v1);
                } else {
                    bf16 h0, l0, h1, l1;
                    split_bf16(v0, h0, l0); split_bf16(v1, h1, l1);
                    *(__nv_bfloat162*)(outhi + pix * kC + oc) = __nv_bfloat162(h0, h1);
                    *(__nv_bfloat162*)(outlo + pix * kC + oc) = __nv_bfloat162(l0, l1);
                    if (EPI == 1)
                        *(float2*)(outf + pix * kC + oc) = make_float2(v0, v1);
                }
            }
        }
}

// ======================= modulated deformable conv =======================
// CTA: one row (128 px) x 128 oc. Per (d,k): gather-sample 128px x 64cg -> smem,
// HMMA against staged weights. Epilogue: leaky(bn) -> hi/lo NHWC.
__global__ void __launch_bounds__(256)
mma_deform_k(const float* __restrict__ h2f, const float* __restrict__ offb,
             const bf16* __restrict__ Whi, const bf16* __restrict__ Wlo,
             const float* __restrict__ scale, const float* __restrict__ shift,
             bf16* __restrict__ outhi, bf16* __restrict__ outlo) {
    constexpr int ASZ = 128 * 144;   // per prec
    constexpr int BSZ = 128 * 144;   // per prec per buf

    extern __shared__ char sm[];
    const uint32_t smA = smem_to_u32(sm);
    const uint32_t smB = smA + 2 * ASZ;

    const int h = blockIdx.x, b = blockIdx.y;
    const int tid = threadIdx.x, wid = tid >> 5, lane = tid & 31;
    const int wm = wid & 3, wn = wid >> 2;
    const int pxb = wm * 32, ocb = wn * 64;
    const int spx = tid >> 1, half = tid & 1;

    float acc[16][4];
#pragma unroll
    for (int i = 0; i < 16; i++)
#pragma unroll
        for (int j = 0; j < 4; j++) acc[i][j] = 0.f;

    auto stageB = [&](int dk, int s) {
#pragma unroll
        for (int it = 0; it < 8; it++) {
            int i = it * 256 + tid;
            int prec = i >> 10, rem = i & 1023, oc = rem >> 3, j = rem & 7;
            const bf16* src = (prec ? Wlo : Whi) + ((size_t)(dk * 128 + oc)) * 64 + j * 8;
            cp16(smB + (s * 2 + prec) * BSZ + oc * 144 + j * 16, src, true);
        }
    };

    const float* op = offb + ((size_t)(b * kHW + h * kW + spx)) * 64;

    stageB(0, 0); cp_commit();
#pragma unroll 1
    for (int dk = 0; dk < 18; dk++) {
        const int s = dk & 1;
        const int d = dk / 9, k = dk % 9;
        // ---- sample A for this (d,k): thread = (px, 32-ch half) ----
        {
            float oy = op[d * 18 + 2 * k], ox = op[d * 18 + 2 * k + 1];
            float ml = op[36 + d * 9 + k];
            float m = 1.f / (1.f + __expf(-ml));
            float py = oy + (float)(h + k / 3 - 1);
            float px = ox + (float)(spx + k % 3 - 1);
            float y0f = floorf(py), x0f = floorf(px);
            float fy = py - y0f, fx = px - x0f;
            int y0 = (int)y0f, x0 = (int)x0f;
            float cw[4] = {(1.f - fy) * (1.f - fx) * m, (1.f - fy) * fx * m,
                           fy * (1.f - fx) * m, fy * fx * m};
            int cy[4] = {y0, y0, y0 + 1, y0 + 1};
            int cx[4] = {x0, x0 + 1, x0, x0 + 1};
#pragma unroll
            for (int g = 0; g < 2; g++) {
                const float* bp = h2f + (size_t)b * kHW * kC + d * 64 + half * 32 + g * 16;
                float rr[16];
#pragma unroll
                for (int j = 0; j < 16; j++) rr[j] = 0.f;
#pragma unroll
                for (int cn = 0; cn < 4; cn++) {
                    int y = cy[cn], x = cx[cn];
                    if (y >= 0 && y < kH && x >= 0 && x < kW) {
                        const float4* p4 = (const float4*)(bp + (size_t)(y * kW + x) * kC);
                        float wg = cw[cn];
#pragma unroll
                        for (int q = 0; q < 4; q++) {
                            float4 u4 = p4[q];
                            rr[q * 4 + 0] += wg * u4.x; rr[q * 4 + 1] += wg * u4.y;
                            rr[q * 4 + 2] += wg * u4.z; rr[q * 4 + 3] += wg * u4.w;
                        }
                    }
                }
                __align__(16) bf16 hb[16], lb[16];
#pragma unroll
                for (int j = 0; j < 16; j++) split_bf16(rr[j], hb[j], lb[j]);
                uint32_t base = spx * 144 + half * 64 + g * 32;
#pragma unroll
                for (int q = 0; q < 2; q++) {
                    *(uint4*)((char*)sm + (smA - smem_to_u32(sm)) + 0 * ASZ + base + q * 16) =
                        ((uint4*)hb)[q];
                    *(uint4*)((char*)sm + (smA - smem_to_u32(sm)) + 1 * ASZ + base + q * 16) =
                        ((uint4*)lb)[q];
                }
            }
        }
        if (dk + 1 < 18) { stageB(dk + 1, s ^ 1); cp_commit(); cp_wait1(); }
        else cp_wait0();
        __syncthreads();
        mma_chunk<2, 4>(smA, smA + ASZ,
                        smB + (s * 2 + 0) * BSZ, smB + (s * 2 + 1) * BSZ,
                        144, 144, pxb, ocb, lane, acc);
        __syncthreads();
    }

    // ---- epilogue: leaky(bn) -> hi/lo NHWC ----
    const int r4 = lane >> 2, cp2 = (lane & 3) * 2;
    const size_t rowbase = (size_t)(b * kHW + h * kW);
#pragma unroll
    for (int mt = 0; mt < 2; mt++)
#pragma unroll
        for (int nt = 0; nt < 8; nt++) {
            const int oc = ocb + nt * 8 + cp2;
            const float s0 = scale[oc], s1 = scale[oc + 1];
            const float sh0 = shift[oc], sh1 = shift[oc + 1];
#pragma unroll
            for (int hh = 0; hh < 2; hh++) {
                const int px = pxb + mt * 16 + r4 + hh * 8;
                float v0 = acc[mt * 8 + nt][hh * 2 + 0] * s0 + sh0;
                float v1 = acc[mt * 8 + nt][hh * 2 + 1] * s1 + sh1;
                v0 = (v0 > 0.f) ? v0 : 0.1f * v0;
                v1 = (v1 > 0.f) ? v1 : 0.1f * v1;
                const size_t pix = rowbase + px;
                bf16 h0, l0, h1, l1;
                split_bf16(v0, h0, l0); split_bf16(v1, h1, l1);
                *(__nv_bfloat162*)(outhi + pix * kC + oc) = __nv_bfloat162(h0, h1);
                *(__nv_bfloat162*)(outlo + pix * kC + oc) = __nv_bfloat162(l0, l1);
            }
        }
}

// ======================= launch =======================
extern "C" void kernel_launch(void* const* d_in, const int* in_sizes, int n_in,
                              void* d_out, int out_size) {
    (void)in_sizes; (void)n_in; (void)out_size;
    const float* x      = (const float*)d_in[0];
    const float* rb_w1  = (const float*)d_in[1];
    const float* rb_b1  = (const float*)d_in[2];
    const float* rb_bn1 = (const float*)d_in[3];
    const float* rb_w2  = (const float*)d_in[4];
    const float* rb_b2  = (const float*)d_in[5];
    const float* rb_bn2 = (const float*)d_in[6];
    const float* off_w  = (const float*)d_in[7];
    const float* off_b  = (const float*)d_in[8];
    const float* dc_w   = (const float*)d_in[9];
    const float* dc_b   = (const float*)d_in[10];
    const float* bn1    = (const float*)d_in[11];
    const float* cv2_w  = (const float*)d_in[12];
    const float* bn2    = (const float*)d_in[13];
    float* out = (float*)d_out;

    float* base = nullptr;
    cudaGetSymbolAddress((void**)&base, g_buf);
    float* xt    = base + O_XT;
    float* h2f   = base + O_H2F;
    float* offb_ = base + O_OFFB;
    bf16* xhi  = (bf16*)(base + O_XHI);
    bf16* xlo  = (bf16*)(base + O_XLO);
    bf16* h1hi = (bf16*)(base + O_H1HI);
    bf16* h1lo = (bf16*)(base + O_H1LO);
    bf16* h2hi = (bf16*)(base + O_H2HI);
    bf16* h2lo = (bf16*)(base + O_H2LO);
    bf16* h3hi = (bf16*)(base + O_H3HI);
    bf16* h3lo = (bf16*)(base + O_H3LO);
    bf16* w1hi = (bf16*)(base + O_W1HI);
    bf16* w1lo = (bf16*)(base + O_W1LO);
    bf16* w2hi = (bf16*)(base + O_W2HI);
    bf16* w2lo = (bf16*)(base + O_W2LO);
    bf16* wdhi = (bf16*)(base + O_WDHI);
    bf16* wdlo = (bf16*)(base + O_WDLO);
    bf16* wohi = (bf16*)(base + O_WOHI);
    bf16* wolo = (bf16*)(base + O_WOLO);
    bf16* wchi = (bf16*)(base + O_WCHI);
    bf16* wclo = (bf16*)(base + O_WCLO);
    float* s1 = base + O_SC;  float* t1 = s1 + kC;
    float* s2 = t1 + kC;      float* t2 = s2 + kC;
    float* s3 = t2 + kC;      float* t3 = s3 + kC;
    float* s4 = t3 + kC;      float* t4 = s4 + kC;
    float* soff = t4 + kC;    float* toff = soff + 64;

    // prep
    wprep3_k<<<(9 * kC * kC + 255) / 256, 256>>>(rb_w1, w1hi, w1lo, kC, kC);
    wprep3_k<<<(9 * kC * kC + 255) / 256, 256>>>(rb_w2, w2hi, w2lo, kC, kC);
    wprep3_k<<<(9 * 64 * kC + 255) / 256, 256>>>(off_w, wohi, wolo, 54, 64);
    wprepdc_k<<<(18 * 128 * 64 + 255) / 256, 256>>>(dc_w, wdhi, wdlo);
    wprep1_k<<<(kC * kC) / 256, 256>>>(cv2_w, wchi, wclo);
    prep_bn_k<<<1, kC>>>(rb_bn1, rb_b1, s1, t1);
    prep_bn_k<<<1, kC>>>(rb_bn2, rb_b2, s2, t2);
    prep_bn_k<<<1, kC>>>(bn1, dc_b, s3, t3);
    prep_bn_k<<<1, kC>>>(bn2, nullptr, s4, t4);
    prep_off_k<<<1, 64>>>(off_b, soff, toff);
    to_nhwc3_k<<<dim3(kHW / 32, kC / 32, kB), dim3(32, 8)>>>(x, xt, xhi, xlo);

    constexpr int SM128 = 4 * (128 * 80) + 4 * (128 * 80);   // 81920
    constexpr int SM64  = 4 * (128 * 80) + 4 * (64 * 80);    // 61440
    constexpr int SMDEF = 2 * (128 * 144) + 4 * (128 * 144); // 110592
    dim3 grid(kH, kB);

    cudaFuncSetAttribute(mma_conv_k<128, 0, 9>, cudaFuncAttributeMaxDynamicSharedMemorySize, SM128);
    cudaFuncSetAttribute(mma_conv_k<128, 1, 9>, cudaFuncAttributeMaxDynamicSharedMemorySize, SM128);
    cudaFuncSetAttribute(mma_conv_k<64, 2, 9>,  cudaFuncAttributeMaxDynamicSharedMemorySize, SM64);
    cudaFuncSetAttribute(mma_conv_k<128, 4, 1>, cudaFuncAttributeMaxDynamicSharedMemorySize, SM128);
    cudaFuncSetAttribute(mma_deform_k,          cudaFuncAttributeMaxDynamicSharedMemorySize, SMDEF);

    mma_conv_k<128, 0, 9><<<grid, 256, SM128>>>(xhi, xlo, w1hi, w1lo, s1, t1,
                                                nullptr, nullptr, h1hi, h1lo);
    mma_conv_k<128, 1, 9><<<grid, 256, SM128>>>(h1hi, h1lo, w2hi, w2lo, s2, t2,
                                                xt, h2f, h2hi, h2lo);
    mma_conv_k<64, 2, 9><<<grid, 256, SM64>>>(h2hi, h2lo, wohi, wolo, soff, toff,
                                              nullptr, offb_, nullptr, nullptr);
    mma_deform_k<<<grid, 256, SMDEF>>>(h2f, offb_, wdhi, wdlo, s3, t3, h3hi, h3lo);
    mma_conv_k<128, 4, 1><<<grid, 256, SM128>>>(h3hi, h3lo, wchi, wclo, s4, t4,
                                                x, out, nullptr, nullptr);
}